// round 1
// baseline (speedup 1.0000x reference)
#include <cuda_runtime.h>
#include <cuda_bf16.h>

#define NN     100000
#define IND    165
#define HID    64

// Scratch (device globals — no allocation allowed)
__device__ float g_y[NN * HID];     // message buffer (A @ Wl)
__device__ float g_agg[NN * HID];   // scatter accumulator
__device__ float g_h[NN * HID];     // root path / layer output
__device__ float g_cnt[NN];         // in-degree

// ---------------------------------------------------------------------------
// Fused dual GEMM: outL = A @ Wl, outR = A @ Wr.  A:[nrows x K] row-major,
// Wl/Wr:[K x 64] row-major. Block tile 64 rows x 128 cols (cols 0..63 = L,
// 64..127 = R), BK=16, 256 threads, 8x4 register micro-tile per thread.
// ---------------------------------------------------------------------------
__global__ void gemm_dual(const float* __restrict__ A, int K, int nrows,
                          const float* __restrict__ Wl,
                          const float* __restrict__ Wr,
                          float* __restrict__ outL,
                          float* __restrict__ outR)
{
    __shared__ __align__(16) float W_s[16][128];
    __shared__ float A_s[64][16];

    const int tid = threadIdx.x;
    const int tx  = tid & 31;   // column group: cols tx*4 .. tx*4+3
    const int ty  = tid >> 5;   // row group:    rows ty*8 .. ty*8+7
    const int row0 = blockIdx.x * 64;

    float acc[8][4];
#pragma unroll
    for (int i = 0; i < 8; i++)
#pragma unroll
        for (int j = 0; j < 4; j++) acc[i][j] = 0.f;

    const int ktiles = (K + 15) >> 4;
    for (int kt = 0; kt < ktiles; kt++) {
        const int k0 = kt << 4;
        // Load A tile [64 x 16] (zero-padded)
        {
            const int r  = tid >> 2;
            const int kb = (tid & 3) << 2;
            const bool rok = (row0 + r) < nrows;
            const float* Ar = A + (long long)(row0 + r) * K;
#pragma unroll
            for (int j = 0; j < 4; j++) {
                const int kk = k0 + kb + j;
                A_s[r][kb + j] = (rok && kk < K) ? Ar[kk] : 0.f;
            }
        }
        // Load W tile [16 x 128] = [Wl | Wr] (zero-padded)
#pragma unroll
        for (int i = 0; i < 8; i++) {
            const int lin = tid + i * 256;
            const int kk = lin >> 7;
            const int c  = lin & 127;
            const int kg = k0 + kk;
            float w = 0.f;
            if (kg < K) w = (c < 64) ? Wl[kg * 64 + c] : Wr[kg * 64 + (c - 64)];
            W_s[kk][c] = w;
        }
        __syncthreads();

#pragma unroll
        for (int kk = 0; kk < 16; kk++) {
            const float4 b = *reinterpret_cast<const float4*>(&W_s[kk][tx * 4]);
#pragma unroll
            for (int i = 0; i < 8; i++) {
                const float a = A_s[ty * 8 + i][kk];   // warp-uniform broadcast
                acc[i][0] += a * b.x;
                acc[i][1] += a * b.y;
                acc[i][2] += a * b.z;
                acc[i][3] += a * b.w;
            }
        }
        __syncthreads();
    }

    float* outp = (tx < 16) ? outL : outR;
    const int c0 = (tx < 16) ? tx * 4 : (tx - 16) * 4;
#pragma unroll
    for (int i = 0; i < 8; i++) {
        const int r = row0 + ty * 8 + i;
        if (r < nrows) {
            float4 v = make_float4(acc[i][0], acc[i][1], acc[i][2], acc[i][3]);
            *reinterpret_cast<float4*>(&outp[r * 64 + c0]) = v;
        }
    }
}

// ---------------------------------------------------------------------------
// In-degree: cnt[dst] += 1 per edge
// ---------------------------------------------------------------------------
__global__ void degree_kernel(const int* __restrict__ ei, int E)
{
    const int e = blockIdx.x * blockDim.x + threadIdx.x;
    if (e < E) atomicAdd(&g_cnt[ei[E + e]], 1.0f);
}

// ---------------------------------------------------------------------------
// Edge scatter: agg[dst] += y[src], 16 threads per edge, float4 vector atomics
// ---------------------------------------------------------------------------
__global__ void scatter_kernel(const int* __restrict__ ei, int E,
                               const float* __restrict__ y)
{
    const int idx = blockIdx.x * blockDim.x + threadIdx.x;
    const int e = idx >> 4;
    if (e >= E) return;
    const int part = (idx & 15) << 2;
    const int src = ei[e];
    const int dst = ei[E + e];
    const float4 v = *reinterpret_cast<const float4*>(&y[src * 64 + part]);
    float* p = &g_agg[dst * 64 + part];
    asm volatile("red.global.add.v4.f32 [%0], {%1, %2, %3, %4};"
                 :: "l"(p), "f"(v.x), "f"(v.y), "f"(v.z), "f"(v.w)
                 : "memory");
}

// ---------------------------------------------------------------------------
// Combine: h = relu(agg / max(cnt,1) + bias + h)   (h holds the root path)
// ---------------------------------------------------------------------------
__global__ void combine_kernel(const float* __restrict__ bias, int n16)
{
    const int idx = blockIdx.x * blockDim.x + threadIdx.x;
    if (idx >= n16) return;
    const int node = idx >> 4;
    const int j4 = (idx & 15) << 2;
    const float inv = 1.0f / fmaxf(g_cnt[node], 1.0f);
    const float4 a = *reinterpret_cast<const float4*>(&g_agg[node * 64 + j4]);
    const float4 r = *reinterpret_cast<const float4*>(&g_h[node * 64 + j4]);
    float4 o;
    o.x = fmaxf(a.x * inv + bias[j4 + 0] + r.x, 0.f);
    o.y = fmaxf(a.y * inv + bias[j4 + 1] + r.y, 0.f);
    o.z = fmaxf(a.z * inv + bias[j4 + 2] + r.z, 0.f);
    o.w = fmaxf(a.w * inv + bias[j4 + 3] + r.w, 0.f);
    *reinterpret_cast<float4*>(&g_h[node * 64 + j4]) = o;
}

// ---------------------------------------------------------------------------
// Classifier: out[n,0:2] = h[n,:] @ Wc + bc
// ---------------------------------------------------------------------------
__global__ void classifier_kernel(const float* __restrict__ Wc,
                                  const float* __restrict__ bc,
                                  float* __restrict__ out, int nrows)
{
    const int n = blockIdx.x * blockDim.x + threadIdx.x;
    if (n >= nrows) return;
    float a0 = bc[0], a1 = bc[1];
    const float* h = &g_h[n * 64];
#pragma unroll
    for (int k = 0; k < 64; k += 4) {
        const float4 hv = *reinterpret_cast<const float4*>(&h[k]);
        a0 += hv.x * Wc[(k + 0) * 2] + hv.y * Wc[(k + 1) * 2]
            + hv.z * Wc[(k + 2) * 2] + hv.w * Wc[(k + 3) * 2];
        a1 += hv.x * Wc[(k + 0) * 2 + 1] + hv.y * Wc[(k + 1) * 2 + 1]
            + hv.z * Wc[(k + 2) * 2 + 1] + hv.w * Wc[(k + 3) * 2 + 1];
    }
    out[n * 2 + 0] = a0;
    out[n * 2 + 1] = a1;
}

// ---------------------------------------------------------------------------
extern "C" void kernel_launch(void* const* d_in, const int* in_sizes, int n_in,
                              void* d_out, int out_size)
{
    const float* x   = (const float*)d_in[0];
    const int*   ei  = (const int*)  d_in[1];
    const float* W1l = (const float*)d_in[2];
    const float* b1  = (const float*)d_in[3];
    const float* W1r = (const float*)d_in[4];
    const float* W2l = (const float*)d_in[5];
    const float* b2  = (const float*)d_in[6];
    const float* W2r = (const float*)d_in[7];
    const float* Wc  = (const float*)d_in[8];
    const float* bc  = (const float*)d_in[9];

    const int N = in_sizes[0] / IND;
    const int E = in_sizes[1] / 2;
    float* out = (float*)d_out;

    void *yp_v, *aggp_v, *hp_v, *cntp_v;
    cudaGetSymbolAddress(&yp_v,   g_y);
    cudaGetSymbolAddress(&aggp_v, g_agg);
    cudaGetSymbolAddress(&hp_v,   g_h);
    cudaGetSymbolAddress(&cntp_v, g_cnt);
    float* yp   = (float*)yp_v;
    float* hp   = (float*)hp_v;

    const int gemm_blocks = (N + 63) / 64;
    const int scat_blocks = (E * 16 + 255) / 256;
    const int comb_blocks = (N * 16 + 255) / 256;

    // Degree (once, shared by both layers)
    cudaMemsetAsync(cntp_v, 0, (size_t)N * sizeof(float));
    degree_kernel<<<(E + 255) / 256, 256>>>(ei, E);

    // ---- Layer 1 ----
    cudaMemsetAsync(aggp_v, 0, (size_t)N * HID * sizeof(float));
    gemm_dual<<<gemm_blocks, 256>>>(x, IND, N, W1l, W1r, yp, hp);
    scatter_kernel<<<scat_blocks, 256>>>(ei, E, yp);
    combine_kernel<<<comb_blocks, 256>>>(b1, N * 16);

    // ---- Layer 2 ----
    cudaMemsetAsync(aggp_v, 0, (size_t)N * HID * sizeof(float));
    gemm_dual<<<gemm_blocks, 256>>>(hp, HID, N, W2l, W2r, yp, hp);
    scatter_kernel<<<scat_blocks, 256>>>(ei, E, yp);
    combine_kernel<<<comb_blocks, 256>>>(b2, N * 16);

    // ---- Classifier ----
    classifier_kernel<<<(N + 127) / 128, 128>>>(Wc, bc, out, N);
}

// round 2
// speedup vs baseline: 1.3117x; 1.3117x over previous
#include <cuda_runtime.h>
#include <cuda_bf16.h>
#include <stdint.h>

#define NN     100000
#define IND    165
#define HID    64

// Scratch (device globals — no allocation allowed)
__device__ float g_y[NN * HID];     // message buffer (A @ Wl)
__device__ float g_agg[NN * HID];   // scatter accumulator
__device__ float g_h[NN * HID];     // root path / layer output
__device__ float g_cnt[NN];         // in-degree

// ---------------------------------------------------------------------------
// bf16-split tensor-core dual GEMM:
//   outL = A @ Wl, outR = A @ Wr   (fp32 in/out, A:[nrows x K] row-major,
//   Wl/Wr:[K x 64] row-major, fused as 128 output cols [L|R])
// Split each fp32 into bf16 hi + bf16 lo; D = Ah*Bh + Ah*Bl + Al*Bh (fp32 acc)
// -> relative error ~2^-16 per product, way under threshold.
// Block: 128 rows x 128 cols, 512 threads = 16 warps (4x4), warp tile 32x32.
// ---------------------------------------------------------------------------
#define MMA_BF16(d, a, b0, b1)                                                 \
  asm volatile(                                                                \
      "mma.sync.aligned.m16n8k16.row.col.f32.bf16.bf16.f32 "                   \
      "{%0,%1,%2,%3},{%4,%5,%6,%7},{%8,%9},{%0,%1,%2,%3};"                     \
      : "+f"(d[0]), "+f"(d[1]), "+f"(d[2]), "+f"(d[3])                         \
      : "r"(a[0]), "r"(a[1]), "r"(a[2]), "r"(a[3]), "r"(b0), "r"(b1))

template <int K, int KPAD, int SA>
__global__ void __launch_bounds__(512, 1)
gemm_mma(const float* __restrict__ A, int nrows,
         const float* __restrict__ Wl, const float* __restrict__ Wr,
         float* __restrict__ outL, float* __restrict__ outR)
{
    constexpr int W = SA / 2;          // u32 words per logical row (k-pairs)
    constexpr int KSTEPS = KPAD / 16;

    extern __shared__ __align__(16) unsigned char smem_raw[];
    __nv_bfloat16* Ah = (__nv_bfloat16*)smem_raw;            // [128][SA]
    __nv_bfloat16* Al = Ah + 128 * SA;                        // [128][SA]
    uint32_t* Ah32 = (uint32_t*)Ah;
    uint32_t* Al32 = (uint32_t*)Al;
    uint32_t* Bh32 = (uint32_t*)(Al + 128 * SA);              // [128][W] u32
    uint32_t* Bl32 = Bh32 + 128 * W;                          // [128][W] u32

    const int tid  = threadIdx.x;
    const int row0 = blockIdx.x * 128;
    int valid = nrows - row0; if (valid > 128) valid = 128;

    // ---- zero A hi/lo (covers k-pad and row-pad) ----
    {
        int4* z = (int4*)smem_raw;
        constexpr int NZ = (2 * 128 * SA * 2) / 16;   // bytes of A region /16
#pragma unroll 4
        for (int i = tid; i < NZ; i += 512) z[i] = make_int4(0, 0, 0, 0);
    }
    __syncthreads();

    // ---- stage A: contiguous float4 reads, scalar bf16 split stores ----
    {
        const float* Ab = A + (size_t)row0 * K;   // 16B aligned (row0 % 4 == 0)
        const int n = valid * K;
        const int n4 = n >> 2;
        for (int i4 = tid; i4 < n4; i4 += 512) {
            float4 v = ((const float4*)Ab)[i4];
            float vals[4] = {v.x, v.y, v.z, v.w};
            const int e0 = i4 << 2;
#pragma unroll
            for (int j = 0; j < 4; j++) {
                const int e = e0 + j;
                const int r = e / K;
                const int k = e - r * K;
                const float x = vals[j];
                const __nv_bfloat16 h = __float2bfloat16(x);
                const float lo = x - __bfloat162float(h);
                Ah[r * SA + k] = h;
                Al[r * SA + k] = __float2bfloat16(lo);
            }
        }
        for (int e = (n & ~3) + tid; e < n; e += 512) {   // tail (usually none)
            const int r = e / K;
            const int k = e - r * K;
            const float x = Ab[e];
            const __nv_bfloat16 h = __float2bfloat16(x);
            Ah[r * SA + k] = h;
            Al[r * SA + k] = __float2bfloat16(x - __bfloat162float(h));
        }
    }

    // ---- stage B (transposed, k-pairs packed; covers pad with zeros) ----
    {
        constexpr int PB = 128 * (KPAD / 2);
        for (int p = tid; p < PB; p += 512) {
            const int c  = (p >> 2) & 127;
            const int k2 = (p & 3) | ((p >> 9) << 2);
            const int k  = k2 * 2;
            const float* Wsrc = (c < 64) ? (Wl + c) : (Wr + (c - 64));
            const float x0 = (k < K)     ? Wsrc[k * 64]       : 0.f;
            const float x1 = (k + 1 < K) ? Wsrc[(k + 1) * 64] : 0.f;
            const __nv_bfloat16 h0 = __float2bfloat16(x0);
            const __nv_bfloat16 h1 = __float2bfloat16(x1);
            const __nv_bfloat16 l0 = __float2bfloat16(x0 - __bfloat162float(h0));
            const __nv_bfloat16 l1 = __float2bfloat16(x1 - __bfloat162float(h1));
            __nv_bfloat162 hp; hp.x = h0; hp.y = h1;
            __nv_bfloat162 lp; lp.x = l0; lp.y = l1;
            Bh32[c * W + k2] = *(const uint32_t*)&hp;
            Bl32[c * W + k2] = *(const uint32_t*)&lp;
        }
    }
    __syncthreads();

    // ---- MMA mainloop ----
    const int lane = tid & 31, wid = tid >> 5;
    const int wm = wid >> 2, wn = wid & 3;       // warp grid 4x4
    const int lr = lane >> 2, lc = lane & 3;

    float acc[2][4][4];
#pragma unroll
    for (int mt = 0; mt < 2; mt++)
#pragma unroll
        for (int nt = 0; nt < 4; nt++)
#pragma unroll
            for (int q = 0; q < 4; q++) acc[mt][nt][q] = 0.f;

    const int ar0 = (wm * 32 + lr) * W + lc;
    const int cb0 = (wn * 32 + lr) * W + lc;

#pragma unroll
    for (int s = 0; s < KSTEPS; s++) {
        const int ko = s * 8;
        uint32_t ah[2][4], al[2][4];
#pragma unroll
        for (int mt = 0; mt < 2; mt++) {
            const int b = ar0 + mt * 16 * W + ko;
            ah[mt][0] = Ah32[b];
            ah[mt][1] = Ah32[b + 8 * W];
            ah[mt][2] = Ah32[b + 4];
            ah[mt][3] = Ah32[b + 8 * W + 4];
            al[mt][0] = Al32[b];
            al[mt][1] = Al32[b + 8 * W];
            al[mt][2] = Al32[b + 4];
            al[mt][3] = Al32[b + 8 * W + 4];
        }
#pragma unroll
        for (int nt = 0; nt < 4; nt++) {
            const int b = cb0 + nt * 8 * W + ko;
            const uint32_t bh0 = Bh32[b], bh1 = Bh32[b + 4];
            const uint32_t bl0 = Bl32[b], bl1 = Bl32[b + 4];
#pragma unroll
            for (int mt = 0; mt < 2; mt++) {
                MMA_BF16(acc[mt][nt], ah[mt], bh0, bh1);
                MMA_BF16(acc[mt][nt], ah[mt], bl0, bl1);
                MMA_BF16(acc[mt][nt], al[mt], bh0, bh1);
            }
        }
    }

    // ---- epilogue ----
#pragma unroll
    for (int mt = 0; mt < 2; mt++) {
#pragma unroll
        for (int nt = 0; nt < 4; nt++) {
            const int colb = wn * 32 + nt * 8;
            float* o = (colb < 64) ? outL : outR;
            const int col = (colb + 2 * lc) & 63;
            const int row = wm * 32 + mt * 16 + lr;
            if (row < valid) {
                float2 v0 = make_float2(acc[mt][nt][0], acc[mt][nt][1]);
                *(float2*)(o + (size_t)(row0 + row) * 64 + col) = v0;
            }
            if (row + 8 < valid) {
                float2 v1 = make_float2(acc[mt][nt][2], acc[mt][nt][3]);
                *(float2*)(o + (size_t)(row0 + row + 8) * 64 + col) = v1;
            }
        }
    }
}

// ---------------------------------------------------------------------------
// In-degree: cnt[dst] += 1 per edge
// ---------------------------------------------------------------------------
__global__ void degree_kernel(const int* __restrict__ ei, int E)
{
    const int e = blockIdx.x * blockDim.x + threadIdx.x;
    if (e < E) atomicAdd(&g_cnt[ei[E + e]], 1.0f);
}

// ---------------------------------------------------------------------------
// Edge scatter: agg[dst] += y[src], 16 threads per edge, float4 vector atomics
// ---------------------------------------------------------------------------
__global__ void scatter_kernel(const int* __restrict__ ei, int E,
                               const float* __restrict__ y)
{
    const int idx = blockIdx.x * blockDim.x + threadIdx.x;
    const int e = idx >> 4;
    if (e >= E) return;
    const int part = (idx & 15) << 2;
    const int src = ei[e];
    const int dst = ei[E + e];
    const float4 v = *reinterpret_cast<const float4*>(&y[src * 64 + part]);
    float* p = &g_agg[dst * 64 + part];
    asm volatile("red.global.add.v4.f32 [%0], {%1, %2, %3, %4};"
                 :: "l"(p), "f"(v.x), "f"(v.y), "f"(v.z), "f"(v.w)
                 : "memory");
}

// ---------------------------------------------------------------------------
// Combine: h = relu(agg / max(cnt,1) + bias + h)   (h holds the root path)
// ---------------------------------------------------------------------------
__global__ void combine_kernel(const float* __restrict__ bias, int n16)
{
    const int idx = blockIdx.x * blockDim.x + threadIdx.x;
    if (idx >= n16) return;
    const int node = idx >> 4;
    const int j4 = (idx & 15) << 2;
    const float inv = 1.0f / fmaxf(g_cnt[node], 1.0f);
    const float4 a = *reinterpret_cast<const float4*>(&g_agg[node * 64 + j4]);
    const float4 r = *reinterpret_cast<const float4*>(&g_h[node * 64 + j4]);
    float4 o;
    o.x = fmaxf(a.x * inv + bias[j4 + 0] + r.x, 0.f);
    o.y = fmaxf(a.y * inv + bias[j4 + 1] + r.y, 0.f);
    o.z = fmaxf(a.z * inv + bias[j4 + 2] + r.z, 0.f);
    o.w = fmaxf(a.w * inv + bias[j4 + 3] + r.w, 0.f);
    *reinterpret_cast<float4*>(&g_h[node * 64 + j4]) = o;
}

// ---------------------------------------------------------------------------
// Classifier: out[n,0:2] = h[n,:] @ Wc + bc
// ---------------------------------------------------------------------------
__global__ void classifier_kernel(const float* __restrict__ Wc,
                                  const float* __restrict__ bc,
                                  float* __restrict__ out, int nrows)
{
    const int n = blockIdx.x * blockDim.x + threadIdx.x;
    if (n >= nrows) return;
    float a0 = bc[0], a1 = bc[1];
    const float* h = &g_h[n * 64];
#pragma unroll
    for (int k = 0; k < 64; k += 4) {
        const float4 hv = *reinterpret_cast<const float4*>(&h[k]);
        a0 += hv.x * Wc[(k + 0) * 2] + hv.y * Wc[(k + 1) * 2]
            + hv.z * Wc[(k + 2) * 2] + hv.w * Wc[(k + 3) * 2];
        a1 += hv.x * Wc[(k + 0) * 2 + 1] + hv.y * Wc[(k + 1) * 2 + 1]
            + hv.z * Wc[(k + 2) * 2 + 1] + hv.w * Wc[(k + 3) * 2 + 1];
    }
    out[n * 2 + 0] = a0;
    out[n * 2 + 1] = a1;
}

// ---------------------------------------------------------------------------
extern "C" void kernel_launch(void* const* d_in, const int* in_sizes, int n_in,
                              void* d_out, int out_size)
{
    const float* x   = (const float*)d_in[0];
    const int*   ei  = (const int*)  d_in[1];
    const float* W1l = (const float*)d_in[2];
    const float* b1  = (const float*)d_in[3];
    const float* W1r = (const float*)d_in[4];
    const float* W2l = (const float*)d_in[5];
    const float* b2  = (const float*)d_in[6];
    const float* W2r = (const float*)d_in[7];
    const float* Wc  = (const float*)d_in[8];
    const float* bc  = (const float*)d_in[9];

    const int N = in_sizes[0] / IND;
    const int E = in_sizes[1] / 2;
    float* out = (float*)d_out;

    void *yp_v, *aggp_v, *hp_v, *cntp_v;
    cudaGetSymbolAddress(&yp_v,   g_y);
    cudaGetSymbolAddress(&aggp_v, g_agg);
    cudaGetSymbolAddress(&hp_v,   g_h);
    cudaGetSymbolAddress(&cntp_v, g_cnt);
    float* yp = (float*)yp_v;
    float* hp = (float*)hp_v;

    // GEMM configs: layer1 K=165 (pad 176, SA=184), layer2 K=64 (SA=72)
    constexpr int SMEM1 = 1024 * 184;   // 188416 B
    constexpr int SMEM2 = 1024 * 72;    //  73728 B
    cudaFuncSetAttribute(gemm_mma<IND, 176, 184>,
                         cudaFuncAttributeMaxDynamicSharedMemorySize, SMEM1);
    cudaFuncSetAttribute(gemm_mma<HID, 64, 72>,
                         cudaFuncAttributeMaxDynamicSharedMemorySize, SMEM2);

    const int gemm_blocks = (N + 127) / 128;
    const int scat_blocks = (E * 16 + 255) / 256;
    const int comb_blocks = (N * 16 + 255) / 256;

    // Degree (once, shared by both layers)
    cudaMemsetAsync(cntp_v, 0, (size_t)N * sizeof(float));
    degree_kernel<<<(E + 255) / 256, 256>>>(ei, E);

    // ---- Layer 1 ----
    cudaMemsetAsync(aggp_v, 0, (size_t)N * HID * sizeof(float));
    gemm_mma<IND, 176, 184><<<gemm_blocks, 512, SMEM1>>>(x, N, W1l, W1r, yp, hp);
    scatter_kernel<<<scat_blocks, 256>>>(ei, E, yp);
    combine_kernel<<<comb_blocks, 256>>>(b1, N * 16);

    // ---- Layer 2 ----
    cudaMemsetAsync(aggp_v, 0, (size_t)N * HID * sizeof(float));
    gemm_mma<HID, 64, 72><<<gemm_blocks, 512, SMEM2>>>(hp, N, W2l, W2r, yp, hp);
    scatter_kernel<<<scat_blocks, 256>>>(ei, E, yp);
    combine_kernel<<<comb_blocks, 256>>>(b2, N * 16);

    // ---- Classifier ----
    classifier_kernel<<<(N + 127) / 128, 128>>>(Wc, bc, out, N);
}

// round 3
// speedup vs baseline: 1.9671x; 1.4996x over previous
#include <cuda_runtime.h>
#include <cuda_bf16.h>
#include <stdint.h>

#define NN     100000
#define EE     1600000
#define IND    165
#define HID    64

// Scratch (device globals — no allocation allowed)
__device__ float g_y[NN * HID];       // message buffer (A @ Wl)
__device__ float g_h[NN * HID];       // root path / layer output
__device__ int   g_deg[NN];           // in-degree (int)
__device__ int   g_off[NN + 1];       // CSR row offsets
__device__ int   g_cursor[NN];        // bucket-fill cursors
__device__ int   g_csr[EE];           // CSR column (src) indices
__device__ int   g_bsum[128];         // scan block sums

// ---------------------------------------------------------------------------
// bf16-split tensor-core dual GEMM (unchanged from R2):
//   outL = A @ Wl, outR = A @ Wr
// ---------------------------------------------------------------------------
#define MMA_BF16(d, a, b0, b1)                                                 \
  asm volatile(                                                                \
      "mma.sync.aligned.m16n8k16.row.col.f32.bf16.bf16.f32 "                   \
      "{%0,%1,%2,%3},{%4,%5,%6,%7},{%8,%9},{%0,%1,%2,%3};"                     \
      : "+f"(d[0]), "+f"(d[1]), "+f"(d[2]), "+f"(d[3])                         \
      : "r"(a[0]), "r"(a[1]), "r"(a[2]), "r"(a[3]), "r"(b0), "r"(b1))

template <int K, int KPAD, int SA>
__global__ void __launch_bounds__(512, 1)
gemm_mma(const float* __restrict__ A, int nrows,
         const float* __restrict__ Wl, const float* __restrict__ Wr,
         float* __restrict__ outL, float* __restrict__ outR)
{
    constexpr int W = SA / 2;
    constexpr int KSTEPS = KPAD / 16;

    extern __shared__ __align__(16) unsigned char smem_raw[];
    __nv_bfloat16* Ah = (__nv_bfloat16*)smem_raw;             // [128][SA]
    __nv_bfloat16* Al = Ah + 128 * SA;
    uint32_t* Ah32 = (uint32_t*)Ah;
    uint32_t* Al32 = (uint32_t*)Al;
    uint32_t* Bh32 = (uint32_t*)(Al + 128 * SA);              // [128][W]
    uint32_t* Bl32 = Bh32 + 128 * W;

    const int tid  = threadIdx.x;
    const int row0 = blockIdx.x * 128;
    int valid = nrows - row0; if (valid > 128) valid = 128;

    {
        int4* z = (int4*)smem_raw;
        constexpr int NZ = (2 * 128 * SA * 2) / 16;
#pragma unroll 4
        for (int i = tid; i < NZ; i += 512) z[i] = make_int4(0, 0, 0, 0);
    }
    __syncthreads();

    {
        const float* Ab = A + (size_t)row0 * K;
        const int n = valid * K;
        const int n4 = n >> 2;
        for (int i4 = tid; i4 < n4; i4 += 512) {
            float4 v = ((const float4*)Ab)[i4];
            float vals[4] = {v.x, v.y, v.z, v.w};
            const int e0 = i4 << 2;
#pragma unroll
            for (int j = 0; j < 4; j++) {
                const int e = e0 + j;
                const int r = e / K;
                const int k = e - r * K;
                const float x = vals[j];
                const __nv_bfloat16 h = __float2bfloat16(x);
                Ah[r * SA + k] = h;
                Al[r * SA + k] = __float2bfloat16(x - __bfloat162float(h));
            }
        }
        for (int e = (n & ~3) + tid; e < n; e += 512) {
            const int r = e / K;
            const int k = e - r * K;
            const float x = Ab[e];
            const __nv_bfloat16 h = __float2bfloat16(x);
            Ah[r * SA + k] = h;
            Al[r * SA + k] = __float2bfloat16(x - __bfloat162float(h));
        }
    }

    {
        constexpr int PB = 128 * (KPAD / 2);
        for (int p = tid; p < PB; p += 512) {
            const int c  = (p >> 2) & 127;
            const int k2 = (p & 3) | ((p >> 9) << 2);
            const int k  = k2 * 2;
            const float* Wsrc = (c < 64) ? (Wl + c) : (Wr + (c - 64));
            const float x0 = (k < K)     ? Wsrc[k * 64]       : 0.f;
            const float x1 = (k + 1 < K) ? Wsrc[(k + 1) * 64] : 0.f;
            const __nv_bfloat16 h0 = __float2bfloat16(x0);
            const __nv_bfloat16 h1 = __float2bfloat16(x1);
            const __nv_bfloat16 l0 = __float2bfloat16(x0 - __bfloat162float(h0));
            const __nv_bfloat16 l1 = __float2bfloat16(x1 - __bfloat162float(h1));
            __nv_bfloat162 hp; hp.x = h0; hp.y = h1;
            __nv_bfloat162 lp; lp.x = l0; lp.y = l1;
            Bh32[c * W + k2] = *(const uint32_t*)&hp;
            Bl32[c * W + k2] = *(const uint32_t*)&lp;
        }
    }
    __syncthreads();

    const int lane = tid & 31, wid = tid >> 5;
    const int wm = wid >> 2, wn = wid & 3;
    const int lr = lane >> 2, lc = lane & 3;

    float acc[2][4][4];
#pragma unroll
    for (int mt = 0; mt < 2; mt++)
#pragma unroll
        for (int nt = 0; nt < 4; nt++)
#pragma unroll
            for (int q = 0; q < 4; q++) acc[mt][nt][q] = 0.f;

    const int ar0 = (wm * 32 + lr) * W + lc;
    const int cb0 = (wn * 32 + lr) * W + lc;

#pragma unroll
    for (int s = 0; s < KSTEPS; s++) {
        const int ko = s * 8;
        uint32_t ah[2][4], al[2][4];
#pragma unroll
        for (int mt = 0; mt < 2; mt++) {
            const int b = ar0 + mt * 16 * W + ko;
            ah[mt][0] = Ah32[b];
            ah[mt][1] = Ah32[b + 8 * W];
            ah[mt][2] = Ah32[b + 4];
            ah[mt][3] = Ah32[b + 8 * W + 4];
            al[mt][0] = Al32[b];
            al[mt][1] = Al32[b + 8 * W];
            al[mt][2] = Al32[b + 4];
            al[mt][3] = Al32[b + 8 * W + 4];
        }
#pragma unroll
        for (int nt = 0; nt < 4; nt++) {
            const int b = cb0 + nt * 8 * W + ko;
            const uint32_t bh0 = Bh32[b], bh1 = Bh32[b + 4];
            const uint32_t bl0 = Bl32[b], bl1 = Bl32[b + 4];
#pragma unroll
            for (int mt = 0; mt < 2; mt++) {
                MMA_BF16(acc[mt][nt], ah[mt], bh0, bh1);
                MMA_BF16(acc[mt][nt], ah[mt], bl0, bl1);
                MMA_BF16(acc[mt][nt], al[mt], bh0, bh1);
            }
        }
    }

#pragma unroll
    for (int mt = 0; mt < 2; mt++) {
#pragma unroll
        for (int nt = 0; nt < 4; nt++) {
            const int colb = wn * 32 + nt * 8;
            float* o = (colb < 64) ? outL : outR;
            const int col = (colb + 2 * lc) & 63;
            const int row = wm * 32 + mt * 16 + lr;
            if (row < valid) {
                float2 v0 = make_float2(acc[mt][nt][0], acc[mt][nt][1]);
                *(float2*)(o + (size_t)(row0 + row) * 64 + col) = v0;
            }
            if (row + 8 < valid) {
                float2 v1 = make_float2(acc[mt][nt][2], acc[mt][nt][3]);
                *(float2*)(o + (size_t)(row0 + row + 8) * 64 + col) = v1;
            }
        }
    }
}

// ---------------------------------------------------------------------------
// CSR construction
// ---------------------------------------------------------------------------
__global__ void degree_int(const int* __restrict__ ei, int E)
{
    const int e = blockIdx.x * blockDim.x + threadIdx.x;
    if (e < E) atomicAdd(&g_deg[ei[E + e]], 1);
}

__global__ void scan1(int n)   // blockDim = 1024
{
    __shared__ int s[1024];
    const int i = blockIdx.x * 1024 + threadIdx.x;
    const int v = (i < n) ? g_deg[i] : 0;
    s[threadIdx.x] = v;
    __syncthreads();
#pragma unroll
    for (int off = 1; off < 1024; off <<= 1) {
        int t = (threadIdx.x >= off) ? s[threadIdx.x - off] : 0;
        __syncthreads();
        s[threadIdx.x] += t;
        __syncthreads();
    }
    if (i < n) g_off[i] = s[threadIdx.x] - v;   // exclusive
    if (threadIdx.x == 1023) g_bsum[blockIdx.x] = s[1023];
}

__global__ void scan2(int nb)
{
    if (threadIdx.x == 0) {
        int acc = 0;
        for (int b = 0; b < nb; b++) { int t = g_bsum[b]; g_bsum[b] = acc; acc += t; }
    }
}

__global__ void scan3(int n, int E)
{
    const int i = blockIdx.x * blockDim.x + threadIdx.x;
    if (i < n) {
        const int o = g_off[i] + g_bsum[i >> 10];
        g_off[i] = o;
        g_cursor[i] = o;
    } else if (i == n) {
        g_off[n] = E;
    }
}

__global__ void csr_fill(const int* __restrict__ ei, int E)
{
    const int e = blockIdx.x * blockDim.x + threadIdx.x;
    if (e >= E) return;
    const int dst = ei[E + e];
    const int pos = atomicAdd(&g_cursor[dst], 1);
    g_csr[pos] = ei[e];
}

// ---------------------------------------------------------------------------
// Fused gather + mean + bias + root + ReLU. 16 lanes per node (float4 each).
// root is read from `hio`, result written back to `hio`.
// ---------------------------------------------------------------------------
__global__ void gather_relu(const float* __restrict__ y,
                            const float* __restrict__ bias,
                            float* __restrict__ hio, int n)
{
    const int tid = threadIdx.x;
    const int node = blockIdx.x * 16 + (tid >> 4);
    if (node >= n) return;
    const int lane4 = (tid & 15) << 2;

    const int s = g_off[node];
    const int e = g_off[node + 1];

    float4 acc = make_float4(0.f, 0.f, 0.f, 0.f);
    int p = s;
    for (; p + 4 <= e; p += 4) {
        const int s0 = g_csr[p], s1 = g_csr[p + 1], s2 = g_csr[p + 2], s3 = g_csr[p + 3];
        const float4 v0 = *(const float4*)&y[(size_t)s0 * 64 + lane4];
        const float4 v1 = *(const float4*)&y[(size_t)s1 * 64 + lane4];
        const float4 v2 = *(const float4*)&y[(size_t)s2 * 64 + lane4];
        const float4 v3 = *(const float4*)&y[(size_t)s3 * 64 + lane4];
        acc.x += v0.x + v1.x + v2.x + v3.x;
        acc.y += v0.y + v1.y + v2.y + v3.y;
        acc.z += v0.z + v1.z + v2.z + v3.z;
        acc.w += v0.w + v1.w + v2.w + v3.w;
    }
    for (; p < e; p++) {
        const int sr = g_csr[p];
        const float4 v = *(const float4*)&y[(size_t)sr * 64 + lane4];
        acc.x += v.x; acc.y += v.y; acc.z += v.z; acc.w += v.w;
    }

    const float inv = 1.0f / fmaxf((float)(e - s), 1.0f);
    const float4 r = *(const float4*)&hio[(size_t)node * 64 + lane4];
    float4 o;
    o.x = fmaxf(acc.x * inv + bias[lane4 + 0] + r.x, 0.f);
    o.y = fmaxf(acc.y * inv + bias[lane4 + 1] + r.y, 0.f);
    o.z = fmaxf(acc.z * inv + bias[lane4 + 2] + r.z, 0.f);
    o.w = fmaxf(acc.w * inv + bias[lane4 + 3] + r.w, 0.f);
    *(float4*)&hio[(size_t)node * 64 + lane4] = o;
}

// ---------------------------------------------------------------------------
// Layer-2 gather with fused classifier: out[node] = relu(...) @ Wc + bc
// ---------------------------------------------------------------------------
__global__ void gather_relu_cls(const float* __restrict__ y,
                                const float* __restrict__ bias,
                                const float* __restrict__ root,
                                const float* __restrict__ Wc,
                                const float* __restrict__ bc,
                                float* __restrict__ out, int n)
{
    const int tid = threadIdx.x;
    const int node = blockIdx.x * 16 + (tid >> 4);
    if (node >= n) return;
    const int lane4 = (tid & 15) << 2;

    const int s = g_off[node];
    const int e = g_off[node + 1];

    float4 acc = make_float4(0.f, 0.f, 0.f, 0.f);
    int p = s;
    for (; p + 4 <= e; p += 4) {
        const int s0 = g_csr[p], s1 = g_csr[p + 1], s2 = g_csr[p + 2], s3 = g_csr[p + 3];
        const float4 v0 = *(const float4*)&y[(size_t)s0 * 64 + lane4];
        const float4 v1 = *(const float4*)&y[(size_t)s1 * 64 + lane4];
        const float4 v2 = *(const float4*)&y[(size_t)s2 * 64 + lane4];
        const float4 v3 = *(const float4*)&y[(size_t)s3 * 64 + lane4];
        acc.x += v0.x + v1.x + v2.x + v3.x;
        acc.y += v0.y + v1.y + v2.y + v3.y;
        acc.z += v0.z + v1.z + v2.z + v3.z;
        acc.w += v0.w + v1.w + v2.w + v3.w;
    }
    for (; p < e; p++) {
        const int sr = g_csr[p];
        const float4 v = *(const float4*)&y[(size_t)sr * 64 + lane4];
        acc.x += v.x; acc.y += v.y; acc.z += v.z; acc.w += v.w;
    }

    const float inv = 1.0f / fmaxf((float)(e - s), 1.0f);
    const float4 r = *(const float4*)&root[(size_t)node * 64 + lane4];
    float h0 = fmaxf(acc.x * inv + bias[lane4 + 0] + r.x, 0.f);
    float h1 = fmaxf(acc.y * inv + bias[lane4 + 1] + r.y, 0.f);
    float h2 = fmaxf(acc.z * inv + bias[lane4 + 2] + r.z, 0.f);
    float h3 = fmaxf(acc.w * inv + bias[lane4 + 3] + r.w, 0.f);

    float p0 = h0 * Wc[(lane4 + 0) * 2] + h1 * Wc[(lane4 + 1) * 2]
             + h2 * Wc[(lane4 + 2) * 2] + h3 * Wc[(lane4 + 3) * 2];
    float p1 = h0 * Wc[(lane4 + 0) * 2 + 1] + h1 * Wc[(lane4 + 1) * 2 + 1]
             + h2 * Wc[(lane4 + 2) * 2 + 1] + h3 * Wc[(lane4 + 3) * 2 + 1];

#pragma unroll
    for (int off = 8; off > 0; off >>= 1) {
        p0 += __shfl_xor_sync(0xffffffffu, p0, off, 16);
        p1 += __shfl_xor_sync(0xffffffffu, p1, off, 16);
    }
    if ((tid & 15) == 0) {
        out[(size_t)node * 2 + 0] = p0 + bc[0];
        out[(size_t)node * 2 + 1] = p1 + bc[1];
    }
}

// ---------------------------------------------------------------------------
extern "C" void kernel_launch(void* const* d_in, const int* in_sizes, int n_in,
                              void* d_out, int out_size)
{
    const float* x   = (const float*)d_in[0];
    const int*   ei  = (const int*)  d_in[1];
    const float* W1l = (const float*)d_in[2];
    const float* b1  = (const float*)d_in[3];
    const float* W1r = (const float*)d_in[4];
    const float* W2l = (const float*)d_in[5];
    const float* b2  = (const float*)d_in[6];
    const float* W2r = (const float*)d_in[7];
    const float* Wc  = (const float*)d_in[8];
    const float* bc  = (const float*)d_in[9];

    const int N = in_sizes[0] / IND;
    const int E = in_sizes[1] / 2;
    float* out = (float*)d_out;

    void *yp_v, *hp_v, *degp_v;
    cudaGetSymbolAddress(&yp_v,   g_y);
    cudaGetSymbolAddress(&hp_v,   g_h);
    cudaGetSymbolAddress(&degp_v, g_deg);
    float* yp = (float*)yp_v;
    float* hp = (float*)hp_v;

    constexpr int SMEM1 = 1024 * 184;
    constexpr int SMEM2 = 1024 * 72;
    cudaFuncSetAttribute(gemm_mma<IND, 176, 184>,
                         cudaFuncAttributeMaxDynamicSharedMemorySize, SMEM1);
    cudaFuncSetAttribute(gemm_mma<HID, 64, 72>,
                         cudaFuncAttributeMaxDynamicSharedMemorySize, SMEM2);

    const int gemm_blocks   = (N + 127) / 128;
    const int scan_blocks   = (N + 1023) / 1024;
    const int gather_blocks = (N + 15) / 16;

    // ---- CSR build ----
    cudaMemsetAsync(degp_v, 0, (size_t)N * sizeof(int));
    degree_int<<<(E + 255) / 256, 256>>>(ei, E);
    scan1<<<scan_blocks, 1024>>>(N);
    scan2<<<1, 32>>>(scan_blocks);
    scan3<<<(N + 256) / 256, 256>>>(N, E);
    csr_fill<<<(E + 255) / 256, 256>>>(ei, E);

    // ---- Layer 1 ----
    gemm_mma<IND, 176, 184><<<gemm_blocks, 512, SMEM1>>>(x, N, W1l, W1r, yp, hp);
    gather_relu<<<gather_blocks, 256>>>(yp, b1, hp, N);

    // ---- Layer 2 + classifier ----
    gemm_mma<HID, 64, 72><<<gemm_blocks, 512, SMEM2>>>(hp, N, W2l, W2r, yp, hp);
    gather_relu_cls<<<gather_blocks, 256>>>(yp, b2, hp, Wc, bc, out, N);
}

// round 4
// speedup vs baseline: 2.3052x; 1.1719x over previous
#include <cuda_runtime.h>
#include <cuda_bf16.h>
#include <cuda_fp16.h>
#include <stdint.h>

#define NN     100000
#define EE     1600000
#define IND    165
#define HID    64

// Scratch (device globals — no allocation allowed)
__device__ __align__(16) unsigned short g_y[NN * HID];  // fp16 message buffer
__device__ float g_h[NN * HID];       // root path / layer output (fp32)
__device__ int   g_deg[NN];           // in-degree (int)
__device__ int   g_off[NN + 1];       // CSR row offsets
__device__ int   g_cursor[NN];        // bucket-fill cursors
__device__ int   g_csr[EE];           // CSR column (src) indices
__device__ int   g_bsum[128];         // scan block sums

// ---------------------------------------------------------------------------
// bf16-split tensor-core dual GEMM:
//   outL = fp16(A @ Wl)  (message path), outR = fp32 A @ Wr (root path)
// ---------------------------------------------------------------------------
#define MMA_BF16(d, a, b0, b1)                                                 \
  asm volatile(                                                                \
      "mma.sync.aligned.m16n8k16.row.col.f32.bf16.bf16.f32 "                   \
      "{%0,%1,%2,%3},{%4,%5,%6,%7},{%8,%9},{%0,%1,%2,%3};"                     \
      : "+f"(d[0]), "+f"(d[1]), "+f"(d[2]), "+f"(d[3])                         \
      : "r"(a[0]), "r"(a[1]), "r"(a[2]), "r"(a[3]), "r"(b0), "r"(b1))

template <int K, int KPAD, int SA>
__global__ void __launch_bounds__(512, 1)
gemm_mma(const float* __restrict__ A, int nrows,
         const float* __restrict__ Wl, const float* __restrict__ Wr,
         __half* __restrict__ outL, float* __restrict__ outR)
{
    constexpr int W = SA / 2;
    constexpr int KSTEPS = KPAD / 16;

    extern __shared__ __align__(16) unsigned char smem_raw[];
    __nv_bfloat16* Ah = (__nv_bfloat16*)smem_raw;             // [128][SA]
    __nv_bfloat16* Al = Ah + 128 * SA;
    uint32_t* Ah32 = (uint32_t*)Ah;
    uint32_t* Al32 = (uint32_t*)Al;
    uint32_t* Bh32 = (uint32_t*)(Al + 128 * SA);              // [128][W]
    uint32_t* Bl32 = Bh32 + 128 * W;

    const int tid  = threadIdx.x;
    const int row0 = blockIdx.x * 128;
    int valid = nrows - row0; if (valid > 128) valid = 128;

    {
        int4* z = (int4*)smem_raw;
        constexpr int NZ = (2 * 128 * SA * 2) / 16;
#pragma unroll 4
        for (int i = tid; i < NZ; i += 512) z[i] = make_int4(0, 0, 0, 0);
    }
    __syncthreads();

    {
        const float* Ab = A + (size_t)row0 * K;
        const int n = valid * K;
        const int n4 = n >> 2;
        for (int i4 = tid; i4 < n4; i4 += 512) {
            float4 v = ((const float4*)Ab)[i4];
            float vals[4] = {v.x, v.y, v.z, v.w};
            const int e0 = i4 << 2;
#pragma unroll
            for (int j = 0; j < 4; j++) {
                const int e = e0 + j;
                const int r = e / K;
                const int k = e - r * K;
                const float x = vals[j];
                const __nv_bfloat16 h = __float2bfloat16(x);
                Ah[r * SA + k] = h;
                Al[r * SA + k] = __float2bfloat16(x - __bfloat162float(h));
            }
        }
        for (int e = (n & ~3) + tid; e < n; e += 512) {
            const int r = e / K;
            const int k = e - r * K;
            const float x = Ab[e];
            const __nv_bfloat16 h = __float2bfloat16(x);
            Ah[r * SA + k] = h;
            Al[r * SA + k] = __float2bfloat16(x - __bfloat162float(h));
        }
    }

    {
        constexpr int PB = 128 * (KPAD / 2);
        for (int p = tid; p < PB; p += 512) {
            const int c  = (p >> 2) & 127;
            const int k2 = (p & 3) | ((p >> 9) << 2);
            const int k  = k2 * 2;
            const float* Wsrc = (c < 64) ? (Wl + c) : (Wr + (c - 64));
            const float x0 = (k < K)     ? Wsrc[k * 64]       : 0.f;
            const float x1 = (k + 1 < K) ? Wsrc[(k + 1) * 64] : 0.f;
            const __nv_bfloat16 h0 = __float2bfloat16(x0);
            const __nv_bfloat16 h1 = __float2bfloat16(x1);
            const __nv_bfloat16 l0 = __float2bfloat16(x0 - __bfloat162float(h0));
            const __nv_bfloat16 l1 = __float2bfloat16(x1 - __bfloat162float(h1));
            __nv_bfloat162 hp; hp.x = h0; hp.y = h1;
            __nv_bfloat162 lp; lp.x = l0; lp.y = l1;
            Bh32[c * W + k2] = *(const uint32_t*)&hp;
            Bl32[c * W + k2] = *(const uint32_t*)&lp;
        }
    }
    __syncthreads();

    const int lane = tid & 31, wid = tid >> 5;
    const int wm = wid >> 2, wn = wid & 3;
    const int lr = lane >> 2, lc = lane & 3;

    float acc[2][4][4];
#pragma unroll
    for (int mt = 0; mt < 2; mt++)
#pragma unroll
        for (int nt = 0; nt < 4; nt++)
#pragma unroll
            for (int q = 0; q < 4; q++) acc[mt][nt][q] = 0.f;

    const int ar0 = (wm * 32 + lr) * W + lc;
    const int cb0 = (wn * 32 + lr) * W + lc;

#pragma unroll
    for (int s = 0; s < KSTEPS; s++) {
        const int ko = s * 8;
        uint32_t ah[2][4], al[2][4];
#pragma unroll
        for (int mt = 0; mt < 2; mt++) {
            const int b = ar0 + mt * 16 * W + ko;
            ah[mt][0] = Ah32[b];
            ah[mt][1] = Ah32[b + 8 * W];
            ah[mt][2] = Ah32[b + 4];
            ah[mt][3] = Ah32[b + 8 * W + 4];
            al[mt][0] = Al32[b];
            al[mt][1] = Al32[b + 8 * W];
            al[mt][2] = Al32[b + 4];
            al[mt][3] = Al32[b + 8 * W + 4];
        }
#pragma unroll
        for (int nt = 0; nt < 4; nt++) {
            const int b = cb0 + nt * 8 * W + ko;
            const uint32_t bh0 = Bh32[b], bh1 = Bh32[b + 4];
            const uint32_t bl0 = Bl32[b], bl1 = Bl32[b + 4];
#pragma unroll
            for (int mt = 0; mt < 2; mt++) {
                MMA_BF16(acc[mt][nt], ah[mt], bh0, bh1);
                MMA_BF16(acc[mt][nt], ah[mt], bl0, bl1);
                MMA_BF16(acc[mt][nt], al[mt], bh0, bh1);
            }
        }
    }

#pragma unroll
    for (int mt = 0; mt < 2; mt++) {
#pragma unroll
        for (int nt = 0; nt < 4; nt++) {
            const int colb = wn * 32 + nt * 8;
            const int col = (colb + 2 * lc) & 63;
            const int row = wm * 32 + mt * 16 + lr;
            if (colb < 64) {
                if (row < valid) {
                    __half2 v = __float22half2_rn(make_float2(acc[mt][nt][0], acc[mt][nt][1]));
                    *(__half2*)(outL + (size_t)(row0 + row) * 64 + col) = v;
                }
                if (row + 8 < valid) {
                    __half2 v = __float22half2_rn(make_float2(acc[mt][nt][2], acc[mt][nt][3]));
                    *(__half2*)(outL + (size_t)(row0 + row + 8) * 64 + col) = v;
                }
            } else {
                if (row < valid) {
                    float2 v0 = make_float2(acc[mt][nt][0], acc[mt][nt][1]);
                    *(float2*)(outR + (size_t)(row0 + row) * 64 + col) = v0;
                }
                if (row + 8 < valid) {
                    float2 v1 = make_float2(acc[mt][nt][2], acc[mt][nt][3]);
                    *(float2*)(outR + (size_t)(row0 + row + 8) * 64 + col) = v1;
                }
            }
        }
    }
}

// ---------------------------------------------------------------------------
// CSR construction
// ---------------------------------------------------------------------------
__global__ void degree_int(const int* __restrict__ ei, int E)
{
    const int e = blockIdx.x * blockDim.x + threadIdx.x;
    if (e < E) atomicAdd(&g_deg[ei[E + e]], 1);
}

__global__ void scan1(int n)   // blockDim = 1024
{
    __shared__ int s[1024];
    const int i = blockIdx.x * 1024 + threadIdx.x;
    const int v = (i < n) ? g_deg[i] : 0;
    s[threadIdx.x] = v;
    __syncthreads();
#pragma unroll
    for (int off = 1; off < 1024; off <<= 1) {
        int t = (threadIdx.x >= off) ? s[threadIdx.x - off] : 0;
        __syncthreads();
        s[threadIdx.x] += t;
        __syncthreads();
    }
    if (i < n) g_off[i] = s[threadIdx.x] - v;   // exclusive
    if (threadIdx.x == 1023) g_bsum[blockIdx.x] = s[1023];
}

__global__ void scan2(int nb)
{
    if (threadIdx.x == 0) {
        int acc = 0;
        for (int b = 0; b < nb; b++) { int t = g_bsum[b]; g_bsum[b] = acc; acc += t; }
    }
}

__global__ void scan3(int n, int E)
{
    const int i = blockIdx.x * blockDim.x + threadIdx.x;
    if (i < n) {
        const int o = g_off[i] + g_bsum[i >> 10];
        g_off[i] = o;
        g_cursor[i] = o;
    } else if (i == n) {
        g_off[n] = E;
    }
}

__global__ void csr_fill(const int* __restrict__ ei, int E)
{
    const int e = blockIdx.x * blockDim.x + threadIdx.x;
    if (e >= E) return;
    const int dst = ei[E + e];
    const int pos = atomicAdd(&g_cursor[dst], 1);
    g_csr[pos] = ei[e];
}

// ---------------------------------------------------------------------------
// Gather accumulation helper: add 8 fp16 values (one uint4) into fp32 acc
// ---------------------------------------------------------------------------
__device__ __forceinline__ void acc_h8(float* acc, const uint4& v)
{
    const __half2* h2 = (const __half2*)&v;
#pragma unroll
    for (int j = 0; j < 4; j++) {
        const float2 f = __half22float2(h2[j]);
        acc[2 * j]     += f.x;
        acc[2 * j + 1] += f.y;
    }
}

// ---------------------------------------------------------------------------
// Fused gather(mean) + bias + root + ReLU. 8 lanes per node (8 fp16 each).
// root read from `hio` (fp32), result written back to `hio`.
// ---------------------------------------------------------------------------
__global__ void gather_relu(const __half* __restrict__ y,
                            const float* __restrict__ bias,
                            float* __restrict__ hio, int n)
{
    const int tid = threadIdx.x;
    const int node = blockIdx.x * 32 + (tid >> 3);
    if (node >= n) return;
    const int l8 = (tid & 7) << 3;

    const int s = g_off[node];
    const int e = g_off[node + 1];

    float acc[8] = {0.f, 0.f, 0.f, 0.f, 0.f, 0.f, 0.f, 0.f};
    int p = s;
    for (; p + 4 <= e; p += 4) {
        const int s0 = g_csr[p], s1 = g_csr[p + 1], s2 = g_csr[p + 2], s3 = g_csr[p + 3];
        const uint4 v0 = *(const uint4*)(y + (size_t)s0 * 64 + l8);
        const uint4 v1 = *(const uint4*)(y + (size_t)s1 * 64 + l8);
        const uint4 v2 = *(const uint4*)(y + (size_t)s2 * 64 + l8);
        const uint4 v3 = *(const uint4*)(y + (size_t)s3 * 64 + l8);
        acc_h8(acc, v0); acc_h8(acc, v1); acc_h8(acc, v2); acc_h8(acc, v3);
    }
    for (; p < e; p++) {
        const uint4 v = *(const uint4*)(y + (size_t)g_csr[p] * 64 + l8);
        acc_h8(acc, v);
    }

    const float inv = 1.0f / fmaxf((float)(e - s), 1.0f);
    float* hrow = hio + (size_t)node * 64 + l8;
    const float4 r0 = *(const float4*)(hrow);
    const float4 r1 = *(const float4*)(hrow + 4);
    float rt[8] = {r0.x, r0.y, r0.z, r0.w, r1.x, r1.y, r1.z, r1.w};
    float o[8];
#pragma unroll
    for (int j = 0; j < 8; j++)
        o[j] = fmaxf(acc[j] * inv + bias[l8 + j] + rt[j], 0.f);
    *(float4*)(hrow)     = make_float4(o[0], o[1], o[2], o[3]);
    *(float4*)(hrow + 4) = make_float4(o[4], o[5], o[6], o[7]);
}

// ---------------------------------------------------------------------------
// Layer-2 gather with fused classifier: out[node] = relu(...) @ Wc + bc
// ---------------------------------------------------------------------------
__global__ void gather_relu_cls(const __half* __restrict__ y,
                                const float* __restrict__ bias,
                                const float* __restrict__ root,
                                const float* __restrict__ Wc,
                                const float* __restrict__ bc,
                                float* __restrict__ out, int n)
{
    const int tid = threadIdx.x;
    const int node = blockIdx.x * 32 + (tid >> 3);
    if (node >= n) return;
    const int l8 = (tid & 7) << 3;

    const int s = g_off[node];
    const int e = g_off[node + 1];

    float acc[8] = {0.f, 0.f, 0.f, 0.f, 0.f, 0.f, 0.f, 0.f};
    int p = s;
    for (; p + 4 <= e; p += 4) {
        const int s0 = g_csr[p], s1 = g_csr[p + 1], s2 = g_csr[p + 2], s3 = g_csr[p + 3];
        const uint4 v0 = *(const uint4*)(y + (size_t)s0 * 64 + l8);
        const uint4 v1 = *(const uint4*)(y + (size_t)s1 * 64 + l8);
        const uint4 v2 = *(const uint4*)(y + (size_t)s2 * 64 + l8);
        const uint4 v3 = *(const uint4*)(y + (size_t)s3 * 64 + l8);
        acc_h8(acc, v0); acc_h8(acc, v1); acc_h8(acc, v2); acc_h8(acc, v3);
    }
    for (; p < e; p++) {
        const uint4 v = *(const uint4*)(y + (size_t)g_csr[p] * 64 + l8);
        acc_h8(acc, v);
    }

    const float inv = 1.0f / fmaxf((float)(e - s), 1.0f);
    const float* rrow = root + (size_t)node * 64 + l8;
    const float4 r0 = *(const float4*)(rrow);
    const float4 r1 = *(const float4*)(rrow + 4);
    float rt[8] = {r0.x, r0.y, r0.z, r0.w, r1.x, r1.y, r1.z, r1.w};

    float p0 = 0.f, p1 = 0.f;
#pragma unroll
    for (int j = 0; j < 8; j++) {
        const float h = fmaxf(acc[j] * inv + bias[l8 + j] + rt[j], 0.f);
        p0 += h * Wc[(l8 + j) * 2];
        p1 += h * Wc[(l8 + j) * 2 + 1];
    }
#pragma unroll
    for (int off = 4; off > 0; off >>= 1) {
        p0 += __shfl_xor_sync(0xffffffffu, p0, off, 8);
        p1 += __shfl_xor_sync(0xffffffffu, p1, off, 8);
    }
    if ((tid & 7) == 0) {
        out[(size_t)node * 2 + 0] = p0 + bc[0];
        out[(size_t)node * 2 + 1] = p1 + bc[1];
    }
}

// ---------------------------------------------------------------------------
extern "C" void kernel_launch(void* const* d_in, const int* in_sizes, int n_in,
                              void* d_out, int out_size)
{
    const float* x   = (const float*)d_in[0];
    const int*   ei  = (const int*)  d_in[1];
    const float* W1l = (const float*)d_in[2];
    const float* b1  = (const float*)d_in[3];
    const float* W1r = (const float*)d_in[4];
    const float* W2l = (const float*)d_in[5];
    const float* b2  = (const float*)d_in[6];
    const float* W2r = (const float*)d_in[7];
    const float* Wc  = (const float*)d_in[8];
    const float* bc  = (const float*)d_in[9];

    const int N = in_sizes[0] / IND;
    const int E = in_sizes[1] / 2;
    float* out = (float*)d_out;

    void *yp_v, *hp_v, *degp_v;
    cudaGetSymbolAddress(&yp_v,   g_y);
    cudaGetSymbolAddress(&hp_v,   g_h);
    cudaGetSymbolAddress(&degp_v, g_deg);
    __half* yp = (__half*)yp_v;
    float*  hp = (float*)hp_v;

    constexpr int SMEM1 = 1024 * 184;
    constexpr int SMEM2 = 1024 * 72;
    cudaFuncSetAttribute(gemm_mma<IND, 176, 184>,
                         cudaFuncAttributeMaxDynamicSharedMemorySize, SMEM1);
    cudaFuncSetAttribute(gemm_mma<HID, 64, 72>,
                         cudaFuncAttributeMaxDynamicSharedMemorySize, SMEM2);

    // One-time side stream + events for forked capture (CSR build || GEMM1)
    static cudaStream_t s_side = nullptr;
    static cudaEvent_t ev_fork = nullptr, ev_join = nullptr;
    if (s_side == nullptr) {
        cudaStreamCreateWithFlags(&s_side, cudaStreamNonBlocking);
        cudaEventCreateWithFlags(&ev_fork, cudaEventDisableTiming);
        cudaEventCreateWithFlags(&ev_join, cudaEventDisableTiming);
    }

    const int gemm_blocks   = (N + 127) / 128;
    const int scan_blocks   = (N + 1023) / 1024;
    const int gather_blocks = (N + 31) / 32;

    // ---- Fork: CSR build on side stream ----
    cudaEventRecord(ev_fork, 0);
    cudaStreamWaitEvent(s_side, ev_fork, 0);
    cudaMemsetAsync(degp_v, 0, (size_t)N * sizeof(int), s_side);
    degree_int<<<(E + 255) / 256, 256, 0, s_side>>>(ei, E);
    scan1<<<scan_blocks, 1024, 0, s_side>>>(N);
    scan2<<<1, 32, 0, s_side>>>(scan_blocks);
    scan3<<<(N + 256) / 256, 256, 0, s_side>>>(N, E);
    csr_fill<<<(E + 255) / 256, 256, 0, s_side>>>(ei, E);
    cudaEventRecord(ev_join, s_side);

    // ---- Main: Layer-1 GEMM concurrently ----
    gemm_mma<IND, 176, 184><<<gemm_blocks, 512, SMEM1>>>(x, N, W1l, W1r, yp, hp);

    // ---- Join, then gathers / layer 2 ----
    cudaStreamWaitEvent(0, ev_join, 0);
    gather_relu<<<gather_blocks, 256>>>(yp, b1, hp, N);

    gemm_mma<HID, 64, 72><<<gemm_blocks, 512, SMEM2>>>(hp, N, W2l, W2r, yp, hp);
    gather_relu_cls<<<gather_blocks, 256>>>(yp, b2, hp, Wc, bc, out, N);
}

// round 5
// speedup vs baseline: 2.5985x; 1.1273x over previous
#include <cuda_runtime.h>
#include <cuda_bf16.h>
#include <cuda_fp16.h>
#include <stdint.h>

#define NN     100000
#define EE     1600000
#define IND    165
#define HID    64

// Scratch (device globals — no allocation allowed)
__device__ __align__(16) unsigned short g_y[NN * HID];  // fp16 message buffer
__device__ float g_h[NN * HID];       // root path / layer output (fp32)
__device__ int   g_deg[NN];           // in-degree (int)
__device__ int   g_off[NN + 1];       // CSR row offsets
__device__ int   g_cursor[NN];        // bucket-fill cursors
__device__ int   g_csr[EE];           // CSR column (src) indices
__device__ int   g_bsum[128];         // scan block sums

// Precomputed bf16-split weight tiles, MMA-ready layout [128 cols][W k2-words]
// Layer1: W=92 (KPAD=176), Layer2: W=36 (KPAD=64)
__device__ __align__(16) uint32_t g_w1h[128 * 92];
__device__ __align__(16) uint32_t g_w1l[128 * 92];
__device__ __align__(16) uint32_t g_w2h[128 * 36];
__device__ __align__(16) uint32_t g_w2l[128 * 36];

// ---------------------------------------------------------------------------
#define MMA_BF16(d, a, b0, b1)                                                 \
  asm volatile(                                                                \
      "mma.sync.aligned.m16n8k16.row.col.f32.bf16.bf16.f32 "                   \
      "{%0,%1,%2,%3},{%4,%5,%6,%7},{%8,%9},{%0,%1,%2,%3};"                     \
      : "+f"(d[0]), "+f"(d[1]), "+f"(d[2]), "+f"(d[3])                         \
      : "r"(a[0]), "r"(a[1]), "r"(a[2]), "r"(a[3]), "r"(b0), "r"(b1))

__device__ __forceinline__ void ldsm_x4(uint32_t* r, uint32_t addr)
{
    asm volatile("ldmatrix.sync.aligned.m8n8.x4.shared.b16 {%0,%1,%2,%3}, [%4];"
                 : "=r"(r[0]), "=r"(r[1]), "=r"(r[2]), "=r"(r[3]) : "r"(addr));
}

// ---------------------------------------------------------------------------
// Weight tile precompute: split fp32 W into bf16 hi/lo, transposed k-pair
// packed layout [128][W] (zero padding beyond K), matching SMEM exactly.
// ---------------------------------------------------------------------------
template <int K, int W>
__device__ __forceinline__ void prep_one(const float* Wl, const float* Wr,
                                         uint32_t* dh, uint32_t* dl, int tid0, int stride)
{
    for (int i = tid0; i < 128 * W; i += stride) {
        const int c  = i / W;
        const int k2 = i - c * W;
        const int k  = k2 * 2;
        uint32_t hw = 0, lw = 0;
        if (k < K) {
            const float* Wsrc = (c < 64) ? (Wl + c) : (Wr + (c - 64));
            const float x0 = Wsrc[k * 64];
            const float x1 = (k + 1 < K) ? Wsrc[(k + 1) * 64] : 0.f;
            const __nv_bfloat16 h0 = __float2bfloat16(x0);
            const __nv_bfloat16 h1 = __float2bfloat16(x1);
            const __nv_bfloat16 l0 = __float2bfloat16(x0 - __bfloat162float(h0));
            const __nv_bfloat16 l1 = __float2bfloat16(x1 - __bfloat162float(h1));
            __nv_bfloat162 hp; hp.x = h0; hp.y = h1;
            __nv_bfloat162 lp; lp.x = l0; lp.y = l1;
            hw = *(const uint32_t*)&hp;
            lw = *(const uint32_t*)&lp;
        }
        dh[i] = hw;
        dl[i] = lw;
    }
}

__global__ void prep_W(const float* __restrict__ W1l, const float* __restrict__ W1r,
                       const float* __restrict__ W2l, const float* __restrict__ W2r)
{
    const int tid0 = blockIdx.x * blockDim.x + threadIdx.x;
    const int stride = gridDim.x * blockDim.x;
    prep_one<IND, 92>(W1l, W1r, g_w1h, g_w1l, tid0, stride);
    prep_one<HID, 36>(W2l, W2r, g_w2h, g_w2l, tid0, stride);
}

// ---------------------------------------------------------------------------
// bf16-split tensor-core dual GEMM:
//   outL = fp16(A @ Wl)  (message path), outR = fp32 A @ Wr (root path)
// B tiles come pre-split/pre-transposed from global (coalesced copy).
// Fragments loaded with ldmatrix.x4.
// ---------------------------------------------------------------------------
template <int K, int KPAD, int SA>
__global__ void __launch_bounds__(512, 1)
gemm_mma(const float* __restrict__ A, int nrows,
         const uint32_t* __restrict__ Wh, const uint32_t* __restrict__ Wlo,
         __half* __restrict__ outL, float* __restrict__ outR)
{
    constexpr int W = SA / 2;
    constexpr int KSTEPS = KPAD / 16;

    extern __shared__ __align__(16) unsigned char smem_raw[];
    __nv_bfloat16* Ah = (__nv_bfloat16*)smem_raw;             // [128][SA]
    __nv_bfloat16* Al = Ah + 128 * SA;
    uint32_t* Bh32 = (uint32_t*)(Al + 128 * SA);              // [128][W]
    uint32_t* Bl32 = Bh32 + 128 * W;

    const int tid  = threadIdx.x;
    const int row0 = blockIdx.x * 128;
    int valid = nrows - row0; if (valid > 128) valid = 128;

    // ---- zero A hi/lo (covers k-pad and row-pad) ----
    {
        int4* z = (int4*)smem_raw;
        constexpr int NZ = (2 * 128 * SA * 2) / 16;
#pragma unroll 4
        for (int i = tid; i < NZ; i += 512) z[i] = make_int4(0, 0, 0, 0);
    }

    // ---- copy precomputed B tiles (coalesced uint4) ----
    {
        constexpr int NB4 = 128 * W / 4;
        const uint4* sh = (const uint4*)Wh;
        const uint4* sl = (const uint4*)Wlo;
        uint4* dh = (uint4*)Bh32;
        uint4* dl = (uint4*)Bl32;
#pragma unroll 2
        for (int i = tid; i < NB4; i += 512) { dh[i] = sh[i]; dl[i] = sl[i]; }
    }
    __syncthreads();

    // ---- stage A: contiguous float4 reads, bf16 split scalar stores ----
    {
        const float* Ab = A + (size_t)row0 * K;
        const int n = valid * K;
        const int n4 = n >> 2;
        for (int i4 = tid; i4 < n4; i4 += 512) {
            float4 v = ((const float4*)Ab)[i4];
            float vals[4] = {v.x, v.y, v.z, v.w};
            const int e0 = i4 << 2;
#pragma unroll
            for (int j = 0; j < 4; j++) {
                const int e = e0 + j;
                const int r = e / K;
                const int k = e - r * K;
                const float x = vals[j];
                const __nv_bfloat16 h = __float2bfloat16(x);
                Ah[r * SA + k] = h;
                Al[r * SA + k] = __float2bfloat16(x - __bfloat162float(h));
            }
        }
        for (int e = (n & ~3) + tid; e < n; e += 512) {
            const int r = e / K;
            const int k = e - r * K;
            const float x = Ab[e];
            const __nv_bfloat16 h = __float2bfloat16(x);
            Ah[r * SA + k] = h;
            Al[r * SA + k] = __float2bfloat16(x - __bfloat162float(h));
        }
    }
    __syncthreads();

    // ---- MMA mainloop (ldmatrix fragments) ----
    const int lane = tid & 31, wid = tid >> 5;
    const int wm = wid >> 2, wn = wid & 3;
    const int lr = lane >> 2, lc = lane & 3;

    const uint32_t AhB = (uint32_t)__cvta_generic_to_shared(Ah);
    const uint32_t AlB = (uint32_t)__cvta_generic_to_shared(Al);
    const uint32_t BhB = (uint32_t)__cvta_generic_to_shared(Bh32);
    const uint32_t BlB = (uint32_t)__cvta_generic_to_shared(Bl32);

    // A frag addr: row = wm*32 + mt*16 + (lane&15), k-block = lane>>4
    const uint32_t a_base = ((wm * 32 + (lane & 15)) * W + ((lane >> 4) << 2)) * 4;
    // B frag addr (x4 covers nt-pair): col = wn*32 + t*16 + (lane&7) + ((lane>>4)<<3),
    // k-block = (lane>>3)&1
    const uint32_t b_base =
        ((wn * 32 + (lane & 7) + ((lane >> 4) << 3)) * W + (((lane >> 3) & 1) << 2)) * 4;

    float acc[2][4][4];
#pragma unroll
    for (int mt = 0; mt < 2; mt++)
#pragma unroll
        for (int nt = 0; nt < 4; nt++)
#pragma unroll
            for (int q = 0; q < 4; q++) acc[mt][nt][q] = 0.f;

#pragma unroll
    for (int s = 0; s < KSTEPS; s++) {
        const uint32_t so = (s * 8) * 4;
        uint32_t ah[2][4], al[2][4];
#pragma unroll
        for (int mt = 0; mt < 2; mt++) {
            const uint32_t off = a_base + so + mt * (16 * W * 4);
            ldsm_x4(ah[mt], AhB + off);
            ldsm_x4(al[mt], AlB + off);
        }
#pragma unroll
        for (int t = 0; t < 2; t++) {
            uint32_t bh[4], bl[4];
            const uint32_t off = b_base + so + t * (16 * W * 4);
            ldsm_x4(bh, BhB + off);
            ldsm_x4(bl, BlB + off);
#pragma unroll
            for (int mt = 0; mt < 2; mt++) {
                MMA_BF16(acc[mt][2 * t],     ah[mt], bh[0], bh[1]);
                MMA_BF16(acc[mt][2 * t],     ah[mt], bl[0], bl[1]);
                MMA_BF16(acc[mt][2 * t],     al[mt], bh[0], bh[1]);
                MMA_BF16(acc[mt][2 * t + 1], ah[mt], bh[2], bh[3]);
                MMA_BF16(acc[mt][2 * t + 1], ah[mt], bl[2], bl[3]);
                MMA_BF16(acc[mt][2 * t + 1], al[mt], bh[2], bh[3]);
            }
        }
    }

    // ---- epilogue ----
#pragma unroll
    for (int mt = 0; mt < 2; mt++) {
#pragma unroll
        for (int nt = 0; nt < 4; nt++) {
            const int colb = wn * 32 + nt * 8;
            const int col = (colb + 2 * lc) & 63;
            const int row = wm * 32 + mt * 16 + lr;
            if (colb < 64) {
                if (row < valid) {
                    __half2 v = __float22half2_rn(make_float2(acc[mt][nt][0], acc[mt][nt][1]));
                    *(__half2*)(outL + (size_t)(row0 + row) * 64 + col) = v;
                }
                if (row + 8 < valid) {
                    __half2 v = __float22half2_rn(make_float2(acc[mt][nt][2], acc[mt][nt][3]));
                    *(__half2*)(outL + (size_t)(row0 + row + 8) * 64 + col) = v;
                }
            } else {
                if (row < valid) {
                    float2 v0 = make_float2(acc[mt][nt][0], acc[mt][nt][1]);
                    *(float2*)(outR + (size_t)(row0 + row) * 64 + col) = v0;
                }
                if (row + 8 < valid) {
                    float2 v1 = make_float2(acc[mt][nt][2], acc[mt][nt][3]);
                    *(float2*)(outR + (size_t)(row0 + row + 8) * 64 + col) = v1;
                }
            }
        }
    }
}

// ---------------------------------------------------------------------------
// CSR construction
// ---------------------------------------------------------------------------
__global__ void degree_int(const int* __restrict__ ei, int E)
{
    const int e = blockIdx.x * blockDim.x + threadIdx.x;
    if (e < E) atomicAdd(&g_deg[ei[E + e]], 1);
}

__global__ void scan1(int n)   // blockDim = 1024
{
    __shared__ int s[1024];
    const int i = blockIdx.x * 1024 + threadIdx.x;
    const int v = (i < n) ? g_deg[i] : 0;
    s[threadIdx.x] = v;
    __syncthreads();
#pragma unroll
    for (int off = 1; off < 1024; off <<= 1) {
        int t = (threadIdx.x >= off) ? s[threadIdx.x - off] : 0;
        __syncthreads();
        s[threadIdx.x] += t;
        __syncthreads();
    }
    if (i < n) g_off[i] = s[threadIdx.x] - v;   // exclusive
    if (threadIdx.x == 1023) g_bsum[blockIdx.x] = s[1023];
}

__global__ void scan2(int nb)
{
    if (threadIdx.x == 0) {
        int acc = 0;
        for (int b = 0; b < nb; b++) { int t = g_bsum[b]; g_bsum[b] = acc; acc += t; }
    }
}

__global__ void scan3(int n, int E)
{
    const int i = blockIdx.x * blockDim.x + threadIdx.x;
    if (i < n) {
        const int o = g_off[i] + g_bsum[i >> 10];
        g_off[i] = o;
        g_cursor[i] = o;
    } else if (i == n) {
        g_off[n] = E;
    }
}

__global__ void csr_fill(const int* __restrict__ ei, int E)
{
    const int e = blockIdx.x * blockDim.x + threadIdx.x;
    if (e >= E) return;
    const int dst = ei[E + e];
    const int pos = atomicAdd(&g_cursor[dst], 1);
    g_csr[pos] = ei[e];
}

// ---------------------------------------------------------------------------
__device__ __forceinline__ void acc_h8(float* acc, const uint4& v)
{
    const __half2* h2 = (const __half2*)&v;
#pragma unroll
    for (int j = 0; j < 4; j++) {
        const float2 f = __half22float2(h2[j]);
        acc[2 * j]     += f.x;
        acc[2 * j + 1] += f.y;
    }
}

// ---------------------------------------------------------------------------
// Fused gather(mean) + bias + root + ReLU. 8 lanes per node (8 fp16 each).
// ---------------------------------------------------------------------------
__global__ void gather_relu(const __half* __restrict__ y,
                            const float* __restrict__ bias,
                            float* __restrict__ hio, int n)
{
    const int tid = threadIdx.x;
    const int node = blockIdx.x * 32 + (tid >> 3);
    if (node >= n) return;
    const int l8 = (tid & 7) << 3;

    const int s = g_off[node];
    const int e = g_off[node + 1];

    float acc[8] = {0.f, 0.f, 0.f, 0.f, 0.f, 0.f, 0.f, 0.f};
    int p = s;
    for (; p + 4 <= e; p += 4) {
        const int s0 = g_csr[p], s1 = g_csr[p + 1], s2 = g_csr[p + 2], s3 = g_csr[p + 3];
        const uint4 v0 = *(const uint4*)(y + (size_t)s0 * 64 + l8);
        const uint4 v1 = *(const uint4*)(y + (size_t)s1 * 64 + l8);
        const uint4 v2 = *(const uint4*)(y + (size_t)s2 * 64 + l8);
        const uint4 v3 = *(const uint4*)(y + (size_t)s3 * 64 + l8);
        acc_h8(acc, v0); acc_h8(acc, v1); acc_h8(acc, v2); acc_h8(acc, v3);
    }
    for (; p < e; p++) {
        const uint4 v = *(const uint4*)(y + (size_t)g_csr[p] * 64 + l8);
        acc_h8(acc, v);
    }

    const float inv = 1.0f / fmaxf((float)(e - s), 1.0f);
    float* hrow = hio + (size_t)node * 64 + l8;
    const float4 r0 = *(const float4*)(hrow);
    const float4 r1 = *(const float4*)(hrow + 4);
    float rt[8] = {r0.x, r0.y, r0.z, r0.w, r1.x, r1.y, r1.z, r1.w};
    float o[8];
#pragma unroll
    for (int j = 0; j < 8; j++)
        o[j] = fmaxf(acc[j] * inv + bias[l8 + j] + rt[j], 0.f);
    *(float4*)(hrow)     = make_float4(o[0], o[1], o[2], o[3]);
    *(float4*)(hrow + 4) = make_float4(o[4], o[5], o[6], o[7]);
}

// ---------------------------------------------------------------------------
// Layer-2 gather with fused classifier: out[node] = relu(...) @ Wc + bc
// ---------------------------------------------------------------------------
__global__ void gather_relu_cls(const __half* __restrict__ y,
                                const float* __restrict__ bias,
                                const float* __restrict__ root,
                                const float* __restrict__ Wc,
                                const float* __restrict__ bc,
                                float* __restrict__ out, int n)
{
    const int tid = threadIdx.x;
    const int node = blockIdx.x * 32 + (tid >> 3);
    if (node >= n) return;
    const int l8 = (tid & 7) << 3;

    const int s = g_off[node];
    const int e = g_off[node + 1];

    float acc[8] = {0.f, 0.f, 0.f, 0.f, 0.f, 0.f, 0.f, 0.f};
    int p = s;
    for (; p + 4 <= e; p += 4) {
        const int s0 = g_csr[p], s1 = g_csr[p + 1], s2 = g_csr[p + 2], s3 = g_csr[p + 3];
        const uint4 v0 = *(const uint4*)(y + (size_t)s0 * 64 + l8);
        const uint4 v1 = *(const uint4*)(y + (size_t)s1 * 64 + l8);
        const uint4 v2 = *(const uint4*)(y + (size_t)s2 * 64 + l8);
        const uint4 v3 = *(const uint4*)(y + (size_t)s3 * 64 + l8);
        acc_h8(acc, v0); acc_h8(acc, v1); acc_h8(acc, v2); acc_h8(acc, v3);
    }
    for (; p < e; p++) {
        const uint4 v = *(const uint4*)(y + (size_t)g_csr[p] * 64 + l8);
        acc_h8(acc, v);
    }

    const float inv = 1.0f / fmaxf((float)(e - s), 1.0f);
    const float* rrow = root + (size_t)node * 64 + l8;
    const float4 r0 = *(const float4*)(rrow);
    const float4 r1 = *(const float4*)(rrow + 4);
    float rt[8] = {r0.x, r0.y, r0.z, r0.w, r1.x, r1.y, r1.z, r1.w};

    float p0 = 0.f, p1 = 0.f;
#pragma unroll
    for (int j = 0; j < 8; j++) {
        const float h = fmaxf(acc[j] * inv + bias[l8 + j] + rt[j], 0.f);
        p0 += h * Wc[(l8 + j) * 2];
        p1 += h * Wc[(l8 + j) * 2 + 1];
    }
#pragma unroll
    for (int off = 4; off > 0; off >>= 1) {
        p0 += __shfl_xor_sync(0xffffffffu, p0, off, 8);
        p1 += __shfl_xor_sync(0xffffffffu, p1, off, 8);
    }
    if ((tid & 7) == 0) {
        out[(size_t)node * 2 + 0] = p0 + bc[0];
        out[(size_t)node * 2 + 1] = p1 + bc[1];
    }
}

// ---------------------------------------------------------------------------
extern "C" void kernel_launch(void* const* d_in, const int* in_sizes, int n_in,
                              void* d_out, int out_size)
{
    const float* x   = (const float*)d_in[0];
    const int*   ei  = (const int*)  d_in[1];
    const float* W1l = (const float*)d_in[2];
    const float* b1  = (const float*)d_in[3];
    const float* W1r = (const float*)d_in[4];
    const float* W2l = (const float*)d_in[5];
    const float* b2  = (const float*)d_in[6];
    const float* W2r = (const float*)d_in[7];
    const float* Wc  = (const float*)d_in[8];
    const float* bc  = (const float*)d_in[9];

    const int N = in_sizes[0] / IND;
    const int E = in_sizes[1] / 2;
    float* out = (float*)d_out;

    void *yp_v, *hp_v, *degp_v;
    void *w1h_v, *w1l_v, *w2h_v, *w2l_v;
    cudaGetSymbolAddress(&yp_v,   g_y);
    cudaGetSymbolAddress(&hp_v,   g_h);
    cudaGetSymbolAddress(&degp_v, g_deg);
    cudaGetSymbolAddress(&w1h_v,  g_w1h);
    cudaGetSymbolAddress(&w1l_v,  g_w1l);
    cudaGetSymbolAddress(&w2h_v,  g_w2h);
    cudaGetSymbolAddress(&w2l_v,  g_w2l);
    __half* yp = (__half*)yp_v;
    float*  hp = (float*)hp_v;

    constexpr int SMEM1 = 1024 * 184;   // A 2x47104 + B 2x47104
    constexpr int SMEM2 = 1024 * 72;
    cudaFuncSetAttribute(gemm_mma<IND, 176, 184>,
                         cudaFuncAttributeMaxDynamicSharedMemorySize, SMEM1);
    cudaFuncSetAttribute(gemm_mma<HID, 64, 72>,
                         cudaFuncAttributeMaxDynamicSharedMemorySize, SMEM2);

    // One-time side stream + events for forked capture
    static cudaStream_t s_side = nullptr;
    static cudaEvent_t ev_fork = nullptr, ev_prep = nullptr, ev_join = nullptr;
    if (s_side == nullptr) {
        cudaStreamCreateWithFlags(&s_side, cudaStreamNonBlocking);
        cudaEventCreateWithFlags(&ev_fork, cudaEventDisableTiming);
        cudaEventCreateWithFlags(&ev_prep, cudaEventDisableTiming);
        cudaEventCreateWithFlags(&ev_join, cudaEventDisableTiming);
    }

    const int gemm_blocks   = (N + 127) / 128;
    const int scan_blocks   = (N + 1023) / 1024;
    const int gather_blocks = (N + 31) / 32;

    // ---- Fork: weight prep then CSR build on side stream ----
    cudaEventRecord(ev_fork, 0);
    cudaStreamWaitEvent(s_side, ev_fork, 0);
    prep_W<<<64, 256, 0, s_side>>>(W1l, W1r, W2l, W2r);
    cudaEventRecord(ev_prep, s_side);
    cudaMemsetAsync(degp_v, 0, (size_t)N * sizeof(int), s_side);
    degree_int<<<(E + 255) / 256, 256, 0, s_side>>>(ei, E);
    scan1<<<scan_blocks, 1024, 0, s_side>>>(N);
    scan2<<<1, 32, 0, s_side>>>(scan_blocks);
    scan3<<<(N + 256) / 256, 256, 0, s_side>>>(N, E);
    csr_fill<<<(E + 255) / 256, 256, 0, s_side>>>(ei, E);
    cudaEventRecord(ev_join, s_side);

    // ---- Main: Layer-1 GEMM (waits only for weight tiles) ----
    cudaStreamWaitEvent(0, ev_prep, 0);
    gemm_mma<IND, 176, 184><<<gemm_blocks, 512, SMEM1>>>(
        x, N, (const uint32_t*)w1h_v, (const uint32_t*)w1l_v, yp, hp);

    // ---- Join CSR, then gathers / layer 2 ----
    cudaStreamWaitEvent(0, ev_join, 0);
    gather_relu<<<gather_blocks, 256>>>(yp, b1, hp, N);

    gemm_mma<HID, 64, 72><<<gemm_blocks, 512, SMEM2>>>(
        hp, N, (const uint32_t*)w2h_v, (const uint32_t*)w2l_v, yp, hp);
    gather_relu_cls<<<gather_blocks, 256>>>(yp, b2, hp, Wc, bc, out, N);
}